// round 4
// baseline (speedup 1.0000x reference)
#include <cuda_runtime.h>

// Scratch (allocation-free rule: __device__ globals)
__device__ float g_pm[32 * 96 * 96 * 96];      // box3(mov), pad 1  -> [32][96][96][96]
__device__ float g_pf[32 * 100 * 100 * 100];   // box3(fix), pad 3  -> [32][100][100][100]

__device__ __forceinline__ float4 ldg4(const float* p) {
    return __ldg(reinterpret_cast<const float4*>(p));
}

__device__ __forceinline__ void cp_async16(void* smem_dst, const void* gmem_src) {
    unsigned sa = (unsigned)__cvta_generic_to_shared(smem_dst);
    asm volatile("cp.async.cg.shared.global [%0], [%1], 16;\n" :: "r"(sa), "l"(gmem_src) : "memory");
}
__device__ __forceinline__ void cp_async_commit() {
    asm volatile("cp.async.commit_group;\n" ::: "memory");
}
__device__ __forceinline__ void cp_async_wait0() {
    asm volatile("cp.async.wait_group 0;\n" ::: "memory");
}

// ---------------------------------------------------------------------------
// Stage 1: 3x3x3 box filter, stride 1, zero pad PAD, output dim O per axis.
// Thread = (c, z-chunk, oy-PAIR, 4-wide x group). Produces TWO output y-rows
// from 4 input rows per z-plane step; horizontal sums via one aligned float4
// + warp shuffles. ZC halved vs R3 to fix occ=35.8% latency exposure.
// ---------------------------------------------------------------------------
template<int O, int PAD, int DST, int ZC>
__global__ __launch_bounds__(256) void box3_kernel(const float* __restrict__ in) {
    constexpr int I   = 96;
    constexpr int XG  = O / 4;
    constexpr int YP  = O / 2;
    constexpr int NCH = (O + ZC - 1) / ZC;
    constexpr int TOT = 32 * YP * XG * NCH;

    const int tid = blockIdx.x * 256 + threadIdx.x;
    if (tid >= TOT) return;                    // warp-aligned exit (TOT % 32 == 0)

    const int lane = threadIdx.x & 31;
    const int xg = tid % XG;
    int t2 = tid / XG;
    const int oyp = t2 % YP;
    t2 /= YP;
    const int zc = t2 % NCH;
    const int c  = t2 / NCH;
    const int bx = xg * 4;
    const int oy0 = oyp * 2;
    const int z0 = zc * ZC;
    const int zend = (z0 + ZC < O) ? (z0 + ZC) : O;

    const float* cin = in + (size_t)c * (I * I * I);
    float* outp = (DST == 0 ? g_pm : g_pf)
                + (size_t)c * (O * O * O) + (size_t)oy0 * O + bx;

    const bool shfl_prev_ok = (lane > 0)  && (xg > 0);
    const bool shfl_next_ok = (lane < 31) && (xg < XG - 1);

    auto plane_sums = [&](int zin, float4& sA, float4& sB) {
        const bool zok = ((unsigned)zin < (unsigned)I);
        const float* zp = cin + (size_t)zin * (I * I);
        float4 rv[4];
#pragma unroll
        for (int t = 0; t < 4; ++t) {
            const int r = oy0 - PAD + t;
            const bool rok = zok && ((unsigned)r < (unsigned)I);
            const float* p = zp + r * I;

            float4 v = make_float4(0.f, 0.f, 0.f, 0.f);
            if (PAD == 1) {
                if (rok) v = ldg4(p + bx);
                float w0 = __shfl_up_sync(0xffffffffu, v.w, 1);
                float w5 = __shfl_down_sync(0xffffffffu, v.x, 1);
                if (!shfl_prev_ok) w0 = (rok && bx > 0)      ? __ldg(p + bx - 1) : 0.f;
                if (!shfl_next_ok) w5 = (rok && bx + 4 < I)  ? __ldg(p + bx + 4) : 0.f;
                rv[t].x = w0 + v.x + v.y;
                rv[t].y = v.x + v.y + v.z;
                rv[t].z = v.y + v.z + v.w;
                rv[t].w = v.z + v.w + w5;
            } else {
                if (rok && bx <= I - 4) v = ldg4(p + bx);
                float py = __shfl_up_sync(0xffffffffu, v.y, 1);
                float pz = __shfl_up_sync(0xffffffffu, v.z, 1);
                float pw = __shfl_up_sync(0xffffffffu, v.w, 1);
                if (!shfl_prev_ok) {
                    if (rok && bx >= 4) {
                        float4 pvv = ldg4(p + bx - 4);
                        py = pvv.y; pz = pvv.z; pw = pvv.w;
                    } else { py = pz = pw = 0.f; }
                }
                rv[t].x = py + pz + pw;
                rv[t].y = pz + pw + v.x;
                rv[t].z = pw + v.x + v.y;
                rv[t].w = v.x + v.y + v.z;
            }
        }
        sA = make_float4(rv[0].x + rv[1].x + rv[2].x, rv[0].y + rv[1].y + rv[2].y,
                         rv[0].z + rv[1].z + rv[2].z, rv[0].w + rv[1].w + rv[2].w);
        sB = make_float4(rv[1].x + rv[2].x + rv[3].x, rv[1].y + rv[2].y + rv[3].y,
                         rv[1].z + rv[2].z + rv[3].z, rv[1].w + rv[2].w + rv[3].w);
    };

    float4 a0, a1, a2, b0, b1, b2;
    plane_sums(z0 - PAD,     a0, b0);
    plane_sums(z0 + 1 - PAD, a1, b1);
    for (int oz = z0; oz < zend; ++oz) {
        plane_sums(oz + 2 - PAD, a2, b2);
        float4 oA = make_float4(a0.x + a1.x + a2.x, a0.y + a1.y + a2.y,
                                a0.z + a1.z + a2.z, a0.w + a1.w + a2.w);
        float4 oB = make_float4(b0.x + b1.x + b2.x, b0.y + b1.y + b2.y,
                                b0.z + b1.z + b2.z, b0.w + b1.w + b2.w);
        float* op = outp + (size_t)oz * (O * O);
        *reinterpret_cast<float4*>(op)     = oA;
        *reinterpret_cast<float4*>(op + O) = oB;
        a0 = a1; a1 = a2; b0 = b1; b1 = b2;
    }
}

// ---------------------------------------------------------------------------
// Stage 2: correlation, k-split. Block tile = 4(z) x 4(y) x 32(x) outputs,
// 384 threads = 3 groups of 128 by x-displacement k. Each thread owns a
// 2x2 (z,y) register block with 9 accumulators (i,j dirs) for its fixed k
// -> 36 acc/thread (was 108), occupancy 12 -> 24 warps/SM.
// pf tile [8][8][36] per channel, double-buffered via cp.async; pm values
// prefetched one channel ahead into registers.
// ---------------------------------------------------------------------------
__global__ __launch_bounds__(384, 2) void corr_kernel(float* __restrict__ out) {
    __shared__ float pfs[2][8][8][36];

    const int kg   = threadIdx.x >> 7;          // 0..2 : x-displacement group
    const int t    = threadIdx.x & 127;
    const int lane = t & 31;
    const int ty   = (t >> 5) & 1;
    const int tz   = t >> 6;
    const int x0 = blockIdx.x * 32;
    const int y0 = blockIdx.y * 4;
    const int z0 = blockIdx.z * 4;

    // tile-load slots: 576 float4 rows over 384 threads (2 slots)
    int s_zz[2], s_yy[2], s_q[2];
    bool s_on[2];
#pragma unroll
    for (int it = 0; it < 2; ++it) {
        const int idx = threadIdx.x + it * 384;
        s_on[it] = idx < 576;
        const int r = idx / 9, q = idx - r * 9;
        s_zz[it] = r >> 3; s_yy[it] = r & 7; s_q[it] = q;
    }

    auto issue_tile = [&](int buf, int c) {
        const float* pfc = g_pf + (size_t)c * 1000000;
#pragma unroll
        for (int it = 0; it < 2; ++it) {
            if (s_on[it]) {
                cp_async16(&pfs[buf][s_zz[it]][s_yy[it]][s_q[it] * 4],
                           pfc + ((z0 + s_zz[it]) * 100 + (y0 + s_yy[it])) * 100
                               + x0 + s_q[it] * 4);
            }
        }
        cp_async_commit();
    };

    size_t pm_off[2][2];
#pragma unroll
    for (int a = 0; a < 2; ++a)
#pragma unroll
        for (int b = 0; b < 2; ++b)
            pm_off[a][b] = (size_t)((z0 + tz + 2 * a) * 96 + (y0 + ty + 2 * b)) * 96
                         + x0 + lane;

    float acc[2][2][9];
#pragma unroll
    for (int a = 0; a < 2; ++a)
#pragma unroll
        for (int b = 0; b < 2; ++b)
#pragma unroll
            for (int d = 0; d < 9; ++d) acc[a][b][d] = 0.f;

    issue_tile(0, 0);

    float pmv[2][2];
#pragma unroll
    for (int a = 0; a < 2; ++a)
#pragma unroll
        for (int b = 0; b < 2; ++b)
            pmv[a][b] = __ldg(g_pm + pm_off[a][b]);

    cp_async_wait0();
    __syncthreads();

#pragma unroll 1
    for (int c = 0; c < 32; ++c) {
        const int cur = c & 1;
        float pmn[2][2];
        if (c < 31) {
            issue_tile(cur ^ 1, c + 1);
            const float* pmc = g_pm + (size_t)(c + 1) * 884736;
#pragma unroll
            for (int a = 0; a < 2; ++a)
#pragma unroll
                for (int b = 0; b < 2; ++b)
                    pmn[a][b] = __ldg(pmc + pm_off[a][b]);
        }

#pragma unroll
        for (int zp = 0; zp < 4; ++zp)
#pragma unroll
            for (int yp = 0; yp < 4; ++yp) {
                const float vk = pfs[cur][tz + 2 * zp][ty + 2 * yp][lane + 2 * kg];
#pragma unroll
                for (int a = 0; a < 2; ++a) {
                    const int i = zp - a;
                    if (i < 0 || i > 2) continue;
#pragma unroll
                    for (int b = 0; b < 2; ++b) {
                        const int j = yp - b;
                        if (j < 0 || j > 2) continue;
                        acc[a][b][i * 3 + j] += pmv[a][b] * vk;
                    }
                }
            }

        if (c < 31) {
            cp_async_wait0();
#pragma unroll
            for (int a = 0; a < 2; ++a)
#pragma unroll
                for (int b = 0; b < 2; ++b)
                    pmv[a][b] = pmn[a][b];
        }
        __syncthreads();
    }

    const float inv = 1.0f / 27.0f;
#pragma unroll
    for (int a = 0; a < 2; ++a)
#pragma unroll
        for (int b = 0; b < 2; ++b) {
            const size_t base = pm_off[a][b];   // output plane layout matches pm
#pragma unroll
            for (int ij = 0; ij < 9; ++ij) {
                const int d = (ij / 3) * 9 + (ij % 3) * 3 + kg;
                out[(size_t)d * 884736 + base] = acc[a][b][ij] * inv;
            }
        }
}

extern "C" void kernel_launch(void* const* d_in, const int* in_sizes, int n_in,
                              void* d_out, int out_size) {
    const float* mov = (const float*)d_in[0];
    const float* fix = (const float*)d_in[1];
    float* out = (float*)d_out;

    // box96: 32c * 48 yp * 24 xg * 12 zc = 442368 threads (1728 blocks)
    box3_kernel<96, 1, 0, 8><<<1728, 256>>>(mov);
    // box100: 32c * 50 yp * 25 xg * 10 zc = 400000 threads (1563 blocks)
    box3_kernel<100, 3, 1, 10><<<1563, 256>>>(fix);

    dim3 cgrid(3, 24, 24);   // x tiles of 32, y/z tiles of 4
    corr_kernel<<<cgrid, 384>>>(out);
}

// round 5
// speedup vs baseline: 1.1017x; 1.1017x over previous
#include <cuda_runtime.h>

// Scratch (allocation-free rule: __device__ globals)
__device__ float g_pm[32 * 96 * 96 * 96];      // box3(mov), pad 1  -> [32][96][96][96]
__device__ float g_pf[32 * 100 * 100 * 100];   // box3(fix), pad 3  -> [32][100][100][100]

__device__ __forceinline__ float4 ldg4(const float* p) {
    return __ldg(reinterpret_cast<const float4*>(p));
}

__device__ __forceinline__ void cp_async16(void* smem_dst, const void* gmem_src) {
    unsigned sa = (unsigned)__cvta_generic_to_shared(smem_dst);
    asm volatile("cp.async.cg.shared.global [%0], [%1], 16;\n" :: "r"(sa), "l"(gmem_src) : "memory");
}
__device__ __forceinline__ void cp_async_commit() {
    asm volatile("cp.async.commit_group;\n" ::: "memory");
}
__device__ __forceinline__ void cp_async_wait0() {
    asm volatile("cp.async.wait_group 0;\n" ::: "memory");
}

// ---------------------------------------------------------------------------
// Stage 1 body: 3x3x3 box filter, stride 1, zero pad PAD, output dim O.
// Virtual thread = (c, z-chunk, oy-PAIR, 4-wide x group). Two output y-rows
// from 4 input rows per z-plane step; horizontal sums via one aligned float4
// + warp shuffles (edge lanes predicated-load fallback).
// ---------------------------------------------------------------------------
template<int O, int PAD, int DST, int ZC>
__device__ __forceinline__ void box3_body(const float* __restrict__ in, int vtid) {
    constexpr int I   = 96;
    constexpr int XG  = O / 4;
    constexpr int YP  = O / 2;
    constexpr int NCH = (O + ZC - 1) / ZC;
    constexpr int TOT = 32 * YP * XG * NCH;

    if (vtid >= TOT) return;                   // warp-aligned (TOT % 32 == 0)

    const int lane = threadIdx.x & 31;
    const int xg = vtid % XG;
    int t2 = vtid / XG;
    const int oyp = t2 % YP;
    t2 /= YP;
    const int zc = t2 % NCH;
    const int c  = t2 / NCH;
    const int bx = xg * 4;
    const int oy0 = oyp * 2;
    const int z0 = zc * ZC;
    const int zend = (z0 + ZC < O) ? (z0 + ZC) : O;

    const float* cin = in + (size_t)c * (I * I * I);
    float* outp = (DST == 0 ? g_pm : g_pf)
                + (size_t)c * (O * O * O) + (size_t)oy0 * O + bx;

    const bool shfl_prev_ok = (lane > 0)  && (xg > 0);
    const bool shfl_next_ok = (lane < 31) && (xg < XG - 1);

    auto plane_sums = [&](int zin, float4& sA, float4& sB) {
        const bool zok = ((unsigned)zin < (unsigned)I);
        const float* zp = cin + (size_t)zin * (I * I);
        float4 rv[4];
#pragma unroll
        for (int t = 0; t < 4; ++t) {
            const int r = oy0 - PAD + t;
            const bool rok = zok && ((unsigned)r < (unsigned)I);
            const float* p = zp + r * I;

            float4 v = make_float4(0.f, 0.f, 0.f, 0.f);
            if (PAD == 1) {
                if (rok) v = ldg4(p + bx);
                float w0 = __shfl_up_sync(0xffffffffu, v.w, 1);
                float w5 = __shfl_down_sync(0xffffffffu, v.x, 1);
                if (!shfl_prev_ok) w0 = (rok && bx > 0)      ? __ldg(p + bx - 1) : 0.f;
                if (!shfl_next_ok) w5 = (rok && bx + 4 < I)  ? __ldg(p + bx + 4) : 0.f;
                rv[t].x = w0 + v.x + v.y;
                rv[t].y = v.x + v.y + v.z;
                rv[t].z = v.y + v.z + v.w;
                rv[t].w = v.z + v.w + w5;
            } else {
                if (rok && bx <= I - 4) v = ldg4(p + bx);
                float py = __shfl_up_sync(0xffffffffu, v.y, 1);
                float pz = __shfl_up_sync(0xffffffffu, v.z, 1);
                float pw = __shfl_up_sync(0xffffffffu, v.w, 1);
                if (!shfl_prev_ok) {
                    if (rok && bx >= 4) {
                        float4 pvv = ldg4(p + bx - 4);
                        py = pvv.y; pz = pvv.z; pw = pvv.w;
                    } else { py = pz = pw = 0.f; }
                }
                rv[t].x = py + pz + pw;
                rv[t].y = pz + pw + v.x;
                rv[t].z = pw + v.x + v.y;
                rv[t].w = v.x + v.y + v.z;
            }
        }
        sA = make_float4(rv[0].x + rv[1].x + rv[2].x, rv[0].y + rv[1].y + rv[2].y,
                         rv[0].z + rv[1].z + rv[2].z, rv[0].w + rv[1].w + rv[2].w);
        sB = make_float4(rv[1].x + rv[2].x + rv[3].x, rv[1].y + rv[2].y + rv[3].y,
                         rv[1].z + rv[2].z + rv[3].z, rv[1].w + rv[2].w + rv[3].w);
    };

    float4 a0, a1, a2, b0, b1, b2;
    plane_sums(z0 - PAD,     a0, b0);
    plane_sums(z0 + 1 - PAD, a1, b1);
    for (int oz = z0; oz < zend; ++oz) {
        plane_sums(oz + 2 - PAD, a2, b2);
        float4 oA = make_float4(a0.x + a1.x + a2.x, a0.y + a1.y + a2.y,
                                a0.z + a1.z + a2.z, a0.w + a1.w + a2.w);
        float4 oB = make_float4(b0.x + b1.x + b2.x, b0.y + b1.y + b2.y,
                                b0.z + b1.z + b2.z, b0.w + b1.w + b2.w);
        float* op = outp + (size_t)oz * (O * O);
        *reinterpret_cast<float4*>(op)     = oA;
        *reinterpret_cast<float4*>(op + O) = oB;
        a0 = a1; a1 = a2; b0 = b1; b1 = b2;
    }
}

// Fused launch: both box filters in one grid so their memory latency overlaps.
// mov needs 1728 virtual blocks, fix needs 1563. Interleave even/odd for the
// first 2*1563 blocks, then the remaining 165 mov blocks.
__global__ __launch_bounds__(256) void box_fused_kernel(
    const float* __restrict__ mov, const float* __restrict__ fix) {
    const int bid = blockIdx.x;
    if (bid < 3126) {
        const int p = bid >> 1;
        if (bid & 1) box3_body<100, 3, 1, 10>(fix, p * 256 + threadIdx.x);
        else         box3_body<96, 1, 0, 8>(mov, p * 256 + threadIdx.x);
    } else {
        const int p = 1563 + (bid - 3126);
        box3_body<96, 1, 0, 8>(mov, p * 256 + threadIdx.x);
    }
}

// ---------------------------------------------------------------------------
// Stage 2: correlation (R3 version — the k-split of R4 regressed by tripling
// per-iteration overhead). Block tile = 4(z) x 4(y) x 32(x), 128 threads.
// Thread owns a 2x2 (z,y) register block, 27 displacement accumulators each.
// pf tile [8][8][36] per channel, double-buffered via cp.async; pm values
// prefetched one channel ahead into registers. (128,3) -> 12 warps/SM.
// ---------------------------------------------------------------------------
__global__ __launch_bounds__(128, 3) void corr_kernel(float* __restrict__ out) {
    __shared__ float pfs[2][8][8][36];

    const int lane = threadIdx.x & 31;
    const int ty   = (threadIdx.x >> 5) & 1;
    const int tz   = threadIdx.x >> 6;
    const int x0 = blockIdx.x * 32;
    const int y0 = blockIdx.y * 4;
    const int z0 = blockIdx.z * 4;

    int s_zz[5], s_yy[5], s_q[5];
    bool s_on[5];
#pragma unroll
    for (int it = 0; it < 5; ++it) {
        const int idx = threadIdx.x + it * 128;
        s_on[it] = idx < 576;
        const int r = idx / 9, q = idx - r * 9;
        s_zz[it] = r >> 3; s_yy[it] = r & 7; s_q[it] = q;
    }

    auto issue_tile = [&](int buf, int c) {
        const float* pfc = g_pf + (size_t)c * 1000000;
#pragma unroll
        for (int it = 0; it < 5; ++it) {
            if (s_on[it]) {
                cp_async16(&pfs[buf][s_zz[it]][s_yy[it]][s_q[it] * 4],
                           pfc + ((z0 + s_zz[it]) * 100 + (y0 + s_yy[it])) * 100
                               + x0 + s_q[it] * 4);
            }
        }
        cp_async_commit();
    };

    size_t pm_off[2][2];
#pragma unroll
    for (int a = 0; a < 2; ++a)
#pragma unroll
        for (int b = 0; b < 2; ++b)
            pm_off[a][b] = (size_t)((z0 + tz + 2 * a) * 96 + (y0 + ty + 2 * b)) * 96
                         + x0 + lane;

    float acc[2][2][27];
#pragma unroll
    for (int a = 0; a < 2; ++a)
#pragma unroll
        for (int b = 0; b < 2; ++b)
#pragma unroll
            for (int d = 0; d < 27; ++d) acc[a][b][d] = 0.f;

    issue_tile(0, 0);

    float pmv[2][2];
#pragma unroll
    for (int a = 0; a < 2; ++a)
#pragma unroll
        for (int b = 0; b < 2; ++b)
            pmv[a][b] = __ldg(g_pm + pm_off[a][b]);

    cp_async_wait0();
    __syncthreads();

#pragma unroll 1
    for (int c = 0; c < 32; ++c) {
        const int cur = c & 1;
        float pmn[2][2];
        if (c < 31) {
            issue_tile(cur ^ 1, c + 1);
            const float* pmc = g_pm + (size_t)(c + 1) * 884736;
#pragma unroll
            for (int a = 0; a < 2; ++a)
#pragma unroll
                for (int b = 0; b < 2; ++b)
                    pmn[a][b] = __ldg(pmc + pm_off[a][b]);
        }

#pragma unroll
        for (int zp = 0; zp < 4; ++zp)
#pragma unroll
            for (int yp = 0; yp < 4; ++yp) {
                const float* bp = &pfs[cur][tz + 2 * zp][ty + 2 * yp][lane];
                const float v0 = bp[0];
                const float v1 = bp[2];
                const float v2 = bp[4];
#pragma unroll
                for (int a = 0; a < 2; ++a) {
                    const int i = zp - a;
                    if (i < 0 || i > 2) continue;
#pragma unroll
                    for (int b = 0; b < 2; ++b) {
                        const int j = yp - b;
                        if (j < 0 || j > 2) continue;
                        const float pv = pmv[a][b];
                        acc[a][b][i * 9 + j * 3 + 0] += pv * v0;
                        acc[a][b][i * 9 + j * 3 + 1] += pv * v1;
                        acc[a][b][i * 9 + j * 3 + 2] += pv * v2;
                    }
                }
            }

        if (c < 31) {
            cp_async_wait0();
#pragma unroll
            for (int a = 0; a < 2; ++a)
#pragma unroll
                for (int b = 0; b < 2; ++b)
                    pmv[a][b] = pmn[a][b];
        }
        __syncthreads();
    }

    const float inv = 1.0f / 27.0f;
#pragma unroll
    for (int a = 0; a < 2; ++a)
#pragma unroll
        for (int b = 0; b < 2; ++b) {
            const size_t base = pm_off[a][b];
#pragma unroll
            for (int d = 0; d < 27; ++d)
                out[(size_t)d * 884736 + base] = acc[a][b][d] * inv;
        }
}

extern "C" void kernel_launch(void* const* d_in, const int* in_sizes, int n_in,
                              void* d_out, int out_size) {
    const float* mov = (const float*)d_in[0];
    const float* fix = (const float*)d_in[1];
    float* out = (float*)d_out;

    // 1728 mov blocks + 1563 fix blocks, interleaved in one grid
    box_fused_kernel<<<3291, 256>>>(mov, fix);

    dim3 cgrid(3, 24, 24);   // x tiles of 32, y/z tiles of 4
    corr_kernel<<<cgrid, 128>>>(out);
}

// round 6
// speedup vs baseline: 1.1862x; 1.0767x over previous
#include <cuda_runtime.h>

// Scratch (allocation-free rule: __device__ globals)
__device__ float g_pm[32 * 96 * 96 * 96];      // box3(mov), pad 1  -> [32][96][96][96]
__device__ float g_pf[32 * 100 * 100 * 100];   // box3(fix), pad 3  -> [32][100][100][100]

__device__ __forceinline__ float4 ldg4(const float* p) {
    return __ldg(reinterpret_cast<const float4*>(p));
}

__device__ __forceinline__ void cp_async16(void* smem_dst, const void* gmem_src) {
    unsigned sa = (unsigned)__cvta_generic_to_shared(smem_dst);
    asm volatile("cp.async.cg.shared.global [%0], [%1], 16;\n" :: "r"(sa), "l"(gmem_src) : "memory");
}
__device__ __forceinline__ void cp_async_commit() {
    asm volatile("cp.async.commit_group;\n" ::: "memory");
}
template<int N>
__device__ __forceinline__ void cp_async_wait() {
    asm volatile("cp.async.wait_group %0;\n" :: "n"(N) : "memory");
}

// ---------------------------------------------------------------------------
// Stage 1 body: 3x3x3 box filter, stride 1, zero pad PAD, output dim O.
// Virtual thread = (c, z-chunk, oy-PAIR, 4-wide x group). Two output y-rows
// from 4 input rows per z-plane step; horizontal sums via one aligned float4
// + warp shuffles (edge lanes predicated-load fallback).
// ---------------------------------------------------------------------------
template<int O, int PAD, int DST, int ZC>
__device__ __forceinline__ void box3_body(const float* __restrict__ in, int vtid) {
    constexpr int I   = 96;
    constexpr int XG  = O / 4;
    constexpr int YP  = O / 2;
    constexpr int NCH = (O + ZC - 1) / ZC;
    constexpr int TOT = 32 * YP * XG * NCH;

    if (vtid >= TOT) return;                   // warp-aligned (TOT % 32 == 0)

    const int lane = threadIdx.x & 31;
    const int xg = vtid % XG;
    int t2 = vtid / XG;
    const int oyp = t2 % YP;
    t2 /= YP;
    const int zc = t2 % NCH;
    const int c  = t2 / NCH;
    const int bx = xg * 4;
    const int oy0 = oyp * 2;
    const int z0 = zc * ZC;
    const int zend = (z0 + ZC < O) ? (z0 + ZC) : O;

    const float* cin = in + (size_t)c * (I * I * I);
    float* outp = (DST == 0 ? g_pm : g_pf)
                + (size_t)c * (O * O * O) + (size_t)oy0 * O + bx;

    const bool shfl_prev_ok = (lane > 0)  && (xg > 0);
    const bool shfl_next_ok = (lane < 31) && (xg < XG - 1);

    auto plane_sums = [&](int zin, float4& sA, float4& sB) {
        const bool zok = ((unsigned)zin < (unsigned)I);
        const float* zp = cin + (size_t)zin * (I * I);
        float4 rv[4];
#pragma unroll
        for (int t = 0; t < 4; ++t) {
            const int r = oy0 - PAD + t;
            const bool rok = zok && ((unsigned)r < (unsigned)I);
            const float* p = zp + r * I;

            float4 v = make_float4(0.f, 0.f, 0.f, 0.f);
            if (PAD == 1) {
                if (rok) v = ldg4(p + bx);
                float w0 = __shfl_up_sync(0xffffffffu, v.w, 1);
                float w5 = __shfl_down_sync(0xffffffffu, v.x, 1);
                if (!shfl_prev_ok) w0 = (rok && bx > 0)      ? __ldg(p + bx - 1) : 0.f;
                if (!shfl_next_ok) w5 = (rok && bx + 4 < I)  ? __ldg(p + bx + 4) : 0.f;
                rv[t].x = w0 + v.x + v.y;
                rv[t].y = v.x + v.y + v.z;
                rv[t].z = v.y + v.z + v.w;
                rv[t].w = v.z + v.w + w5;
            } else {
                if (rok && bx <= I - 4) v = ldg4(p + bx);
                float py = __shfl_up_sync(0xffffffffu, v.y, 1);
                float pz = __shfl_up_sync(0xffffffffu, v.z, 1);
                float pw = __shfl_up_sync(0xffffffffu, v.w, 1);
                if (!shfl_prev_ok) {
                    if (rok && bx >= 4) {
                        float4 pvv = ldg4(p + bx - 4);
                        py = pvv.y; pz = pvv.z; pw = pvv.w;
                    } else { py = pz = pw = 0.f; }
                }
                rv[t].x = py + pz + pw;
                rv[t].y = pz + pw + v.x;
                rv[t].z = pw + v.x + v.y;
                rv[t].w = v.x + v.y + v.z;
            }
        }
        sA = make_float4(rv[0].x + rv[1].x + rv[2].x, rv[0].y + rv[1].y + rv[2].y,
                         rv[0].z + rv[1].z + rv[2].z, rv[0].w + rv[1].w + rv[2].w);
        sB = make_float4(rv[1].x + rv[2].x + rv[3].x, rv[1].y + rv[2].y + rv[3].y,
                         rv[1].z + rv[2].z + rv[3].z, rv[1].w + rv[2].w + rv[3].w);
    };

    float4 a0, a1, a2, b0, b1, b2;
    plane_sums(z0 - PAD,     a0, b0);
    plane_sums(z0 + 1 - PAD, a1, b1);
    for (int oz = z0; oz < zend; ++oz) {
        plane_sums(oz + 2 - PAD, a2, b2);
        float4 oA = make_float4(a0.x + a1.x + a2.x, a0.y + a1.y + a2.y,
                                a0.z + a1.z + a2.z, a0.w + a1.w + a2.w);
        float4 oB = make_float4(b0.x + b1.x + b2.x, b0.y + b1.y + b2.y,
                                b0.z + b1.z + b2.z, b0.w + b1.w + b2.w);
        float* op = outp + (size_t)oz * (O * O);
        *reinterpret_cast<float4*>(op)     = oA;
        *reinterpret_cast<float4*>(op + O) = oB;
        a0 = a1; a1 = a2; b0 = b1; b1 = b2;
    }
}

// Fused launch: both box filters in one grid so their memory latency overlaps.
__global__ __launch_bounds__(256) void box_fused_kernel(
    const float* __restrict__ mov, const float* __restrict__ fix) {
    const int bid = blockIdx.x;
    if (bid < 3126) {
        const int p = bid >> 1;
        if (bid & 1) box3_body<100, 3, 1, 10>(fix, p * 256 + threadIdx.x);
        else         box3_body<96, 1, 0, 8>(mov, p * 256 + threadIdx.x);
    } else {
        const int p = 1563 + (bid - 3126);
        box3_body<96, 1, 0, 8>(mov, p * 256 + threadIdx.x);
    }
}

// ---------------------------------------------------------------------------
// Stage 2: correlation. Block tile = 4(z) x 4(y) x 32(x), 128 threads, thread
// owns a 2x2 (z,y) block with 27 accumulators each. R5 profile showed pure
// latency exposure (occ 17.7%, issue 28.6%, all pipes idle): the pf tile
// pipeline was 1-deep, exposing ~DRAM latency every channel. Now 3-deep
// (4 smem buffers, wait_group<=2); empty commit groups keep the invariant
// in the tail. Buffer overwrite at iter c targets buf[(c+3)&3], whose readers
// (iter c-1) all passed the sync at the top of iter c.
// ---------------------------------------------------------------------------
__global__ __launch_bounds__(128, 3) void corr_kernel(float* __restrict__ out) {
    __shared__ float pfs[4][8][8][36];

    const int lane = threadIdx.x & 31;
    const int ty   = (threadIdx.x >> 5) & 1;
    const int tz   = threadIdx.x >> 6;
    const int x0 = blockIdx.x * 32;
    const int y0 = blockIdx.y * 4;
    const int z0 = blockIdx.z * 4;

    int s_zz[5], s_yy[5], s_q[5];
    bool s_on[5];
#pragma unroll
    for (int it = 0; it < 5; ++it) {
        const int idx = threadIdx.x + it * 128;
        s_on[it] = idx < 576;
        const int r = idx / 9, q = idx - r * 9;
        s_zz[it] = r >> 3; s_yy[it] = r & 7; s_q[it] = q;
    }

    auto issue_tile = [&](int c) {   // always commits (empty group past c=31)
        if (c < 32) {
            const int buf = c & 3;
            const float* pfc = g_pf + (size_t)c * 1000000;
#pragma unroll
            for (int it = 0; it < 5; ++it) {
                if (s_on[it]) {
                    cp_async16(&pfs[buf][s_zz[it]][s_yy[it]][s_q[it] * 4],
                               pfc + ((z0 + s_zz[it]) * 100 + (y0 + s_yy[it])) * 100
                                   + x0 + s_q[it] * 4);
                }
            }
        }
        cp_async_commit();
    };

    size_t pm_off[2][2];
#pragma unroll
    for (int a = 0; a < 2; ++a)
#pragma unroll
        for (int b = 0; b < 2; ++b)
            pm_off[a][b] = (size_t)((z0 + tz + 2 * a) * 96 + (y0 + ty + 2 * b)) * 96
                         + x0 + lane;

    float acc[2][2][27];
#pragma unroll
    for (int a = 0; a < 2; ++a)
#pragma unroll
        for (int b = 0; b < 2; ++b)
#pragma unroll
            for (int d = 0; d < 27; ++d) acc[a][b][d] = 0.f;

    // 3-deep prologue
    issue_tile(0);
    issue_tile(1);
    issue_tile(2);

    float pmv[2][2];
#pragma unroll
    for (int a = 0; a < 2; ++a)
#pragma unroll
        for (int b = 0; b < 2; ++b)
            pmv[a][b] = __ldg(g_pm + pm_off[a][b]);

#pragma unroll 1
    for (int c = 0; c < 32; ++c) {
        cp_async_wait<2>();          // tile c complete (3 groups outstanding)
        __syncthreads();             // visibility + buf[(c+3)&3] readers done
        issue_tile(c + 3);

        float pmn[2][2];
        if (c < 31) {
            const float* pmc = g_pm + (size_t)(c + 1) * 884736;
#pragma unroll
            for (int a = 0; a < 2; ++a)
#pragma unroll
                for (int b = 0; b < 2; ++b)
                    pmn[a][b] = __ldg(pmc + pm_off[a][b]);
        }

        const int cur = c & 3;
#pragma unroll
        for (int zp = 0; zp < 4; ++zp)
#pragma unroll
            for (int yp = 0; yp < 4; ++yp) {
                const float* bp = &pfs[cur][tz + 2 * zp][ty + 2 * yp][lane];
                const float v0 = bp[0];
                const float v1 = bp[2];
                const float v2 = bp[4];
#pragma unroll
                for (int a = 0; a < 2; ++a) {
                    const int i = zp - a;
                    if (i < 0 || i > 2) continue;
#pragma unroll
                    for (int b = 0; b < 2; ++b) {
                        const int j = yp - b;
                        if (j < 0 || j > 2) continue;
                        const float pv = pmv[a][b];
                        acc[a][b][i * 9 + j * 3 + 0] += pv * v0;
                        acc[a][b][i * 9 + j * 3 + 1] += pv * v1;
                        acc[a][b][i * 9 + j * 3 + 2] += pv * v2;
                    }
                }
            }

        if (c < 31) {
#pragma unroll
            for (int a = 0; a < 2; ++a)
#pragma unroll
                for (int b = 0; b < 2; ++b)
                    pmv[a][b] = pmn[a][b];
        }
    }

    const float inv = 1.0f / 27.0f;
#pragma unroll
    for (int a = 0; a < 2; ++a)
#pragma unroll
        for (int b = 0; b < 2; ++b) {
            const size_t base = pm_off[a][b];
#pragma unroll
            for (int d = 0; d < 27; ++d)
                out[(size_t)d * 884736 + base] = acc[a][b][d] * inv;
        }
}

extern "C" void kernel_launch(void* const* d_in, const int* in_sizes, int n_in,
                              void* d_out, int out_size) {
    const float* mov = (const float*)d_in[0];
    const float* fix = (const float*)d_in[1];
    float* out = (float*)d_out;

    box_fused_kernel<<<3291, 256>>>(mov, fix);

    dim3 cgrid(3, 24, 24);   // x tiles of 32, y/z tiles of 4
    corr_kernel<<<cgrid, 128>>>(out);
}

// round 7
// speedup vs baseline: 1.3591x; 1.1458x over previous
#include <cuda_runtime.h>

// Scratch (allocation-free rule: __device__ globals)
__device__ float g_pm[32 * 96 * 96 * 96];      // box3(mov), pad 1  -> [32][96][96][96]
__device__ float g_pf[32 * 100 * 100 * 100];   // box3(fix), pad 3  -> [32][100][100][100]

__device__ __forceinline__ float4 ldg4(const float* p) {
    return __ldg(reinterpret_cast<const float4*>(p));
}

__device__ __forceinline__ void cp_async16(void* smem_dst, const void* gmem_src) {
    unsigned sa = (unsigned)__cvta_generic_to_shared(smem_dst);
    asm volatile("cp.async.cg.shared.global [%0], [%1], 16;\n" :: "r"(sa), "l"(gmem_src) : "memory");
}
__device__ __forceinline__ void cp_async_commit() {
    asm volatile("cp.async.commit_group;\n" ::: "memory");
}
template<int N>
__device__ __forceinline__ void cp_async_wait() {
    asm volatile("cp.async.wait_group %0;\n" :: "n"(N) : "memory");
}

// ---------------------------------------------------------------------------
// Stage 1 body: 3x3x3 box filter, stride 1, zero pad PAD, output dim O.
// Virtual thread = (c, z-chunk, oy-PAIR, 4-wide x group). Two output y-rows
// from 4 input rows per z-plane step; horizontal sums via one aligned float4
// + warp shuffles (edge lanes predicated-load fallback).
// ---------------------------------------------------------------------------
template<int O, int PAD, int DST, int ZC>
__device__ __forceinline__ void box3_body(const float* __restrict__ in, int vtid) {
    constexpr int I   = 96;
    constexpr int XG  = O / 4;
    constexpr int YP  = O / 2;
    constexpr int NCH = (O + ZC - 1) / ZC;
    constexpr int TOT = 32 * YP * XG * NCH;

    if (vtid >= TOT) return;                   // warp-aligned (TOT % 32 == 0)

    const int lane = threadIdx.x & 31;
    const int xg = vtid % XG;
    int t2 = vtid / XG;
    const int oyp = t2 % YP;
    t2 /= YP;
    const int zc = t2 % NCH;
    const int c  = t2 / NCH;
    const int bx = xg * 4;
    const int oy0 = oyp * 2;
    const int z0 = zc * ZC;
    const int zend = (z0 + ZC < O) ? (z0 + ZC) : O;

    const float* cin = in + (size_t)c * (I * I * I);
    float* outp = (DST == 0 ? g_pm : g_pf)
                + (size_t)c * (O * O * O) + (size_t)oy0 * O + bx;

    const bool shfl_prev_ok = (lane > 0)  && (xg > 0);
    const bool shfl_next_ok = (lane < 31) && (xg < XG - 1);

    auto plane_sums = [&](int zin, float4& sA, float4& sB) {
        const bool zok = ((unsigned)zin < (unsigned)I);
        const float* zp = cin + (size_t)zin * (I * I);
        float4 rv[4];
#pragma unroll
        for (int t = 0; t < 4; ++t) {
            const int r = oy0 - PAD + t;
            const bool rok = zok && ((unsigned)r < (unsigned)I);
            const float* p = zp + r * I;

            float4 v = make_float4(0.f, 0.f, 0.f, 0.f);
            if (PAD == 1) {
                if (rok) v = ldg4(p + bx);
                float w0 = __shfl_up_sync(0xffffffffu, v.w, 1);
                float w5 = __shfl_down_sync(0xffffffffu, v.x, 1);
                if (!shfl_prev_ok) w0 = (rok && bx > 0)      ? __ldg(p + bx - 1) : 0.f;
                if (!shfl_next_ok) w5 = (rok && bx + 4 < I)  ? __ldg(p + bx + 4) : 0.f;
                rv[t].x = w0 + v.x + v.y;
                rv[t].y = v.x + v.y + v.z;
                rv[t].z = v.y + v.z + v.w;
                rv[t].w = v.z + v.w + w5;
            } else {
                if (rok && bx <= I - 4) v = ldg4(p + bx);
                float py = __shfl_up_sync(0xffffffffu, v.y, 1);
                float pz = __shfl_up_sync(0xffffffffu, v.z, 1);
                float pw = __shfl_up_sync(0xffffffffu, v.w, 1);
                if (!shfl_prev_ok) {
                    if (rok && bx >= 4) {
                        float4 pvv = ldg4(p + bx - 4);
                        py = pvv.y; pz = pvv.z; pw = pvv.w;
                    } else { py = pz = pw = 0.f; }
                }
                rv[t].x = py + pz + pw;
                rv[t].y = pz + pw + v.x;
                rv[t].z = pw + v.x + v.y;
                rv[t].w = v.x + v.y + v.z;
            }
        }
        sA = make_float4(rv[0].x + rv[1].x + rv[2].x, rv[0].y + rv[1].y + rv[2].y,
                         rv[0].z + rv[1].z + rv[2].z, rv[0].w + rv[1].w + rv[2].w);
        sB = make_float4(rv[1].x + rv[2].x + rv[3].x, rv[1].y + rv[2].y + rv[3].y,
                         rv[1].z + rv[2].z + rv[3].z, rv[1].w + rv[2].w + rv[3].w);
    };

    float4 a0, a1, a2, b0, b1, b2;
    plane_sums(z0 - PAD,     a0, b0);
    plane_sums(z0 + 1 - PAD, a1, b1);
    for (int oz = z0; oz < zend; ++oz) {
        plane_sums(oz + 2 - PAD, a2, b2);
        float4 oA = make_float4(a0.x + a1.x + a2.x, a0.y + a1.y + a2.y,
                                a0.z + a1.z + a2.z, a0.w + a1.w + a2.w);
        float4 oB = make_float4(b0.x + b1.x + b2.x, b0.y + b1.y + b2.y,
                                b0.z + b1.z + b2.z, b0.w + b1.w + b2.w);
        float* op = outp + (size_t)oz * (O * O);
        *reinterpret_cast<float4*>(op)     = oA;
        *reinterpret_cast<float4*>(op + O) = oB;
        a0 = a1; a1 = a2; b0 = b1; b1 = b2;
    }
}

// Fused launch: both box filters in one grid so their memory latency overlaps.
__global__ __launch_bounds__(256) void box_fused_kernel(
    const float* __restrict__ mov, const float* __restrict__ fix) {
    const int bid = blockIdx.x;
    if (bid < 3126) {
        const int p = bid >> 1;
        if (bid & 1) box3_body<100, 3, 1, 10>(fix, p * 256 + threadIdx.x);
        else         box3_body<96, 1, 0, 8>(mov, p * 256 + threadIdx.x);
    } else {
        const int p = 1563 + (bid - 3126);
        box3_body<96, 1, 0, 8>(mov, p * 256 + threadIdx.x);
    }
}

// ---------------------------------------------------------------------------
// Stage 2: correlation. Block tile = 4(z) x 4(y) x 32(x), 128 threads.
// Thread owns a 2x2 (z,y) block, 27 accumulators each.
//
// R6 insight: the four warps read DISJOINT pf rows (warp's (tz,ty) fixes the
// z- and y-parity of every row it touches). So the pf tile is split into
// per-warp PRIVATE regions: each warp cp.asyncs its own 16 rows, waits on its
// own groups, and publishes intra-warp with __syncwarp. NO __syncthreads in
// the channel loop — warps fully decoupled (R6 showed barrier-coupled stalls:
// issue 28.7% with fetch latency already covered by the 3-deep pipeline).
// Buffer reuse is program-order-safe: buf[(c+3)&3] was last read by THIS warp
// in iteration c-1.
// ---------------------------------------------------------------------------
__global__ __launch_bounds__(128, 3) void corr_kernel(float* __restrict__ out) {
    // [buf][warp][row r=zp*4+yp][36]  : row holds z=2*(r>>2)+tz, y=2*(r&3)+ty
    __shared__ float pfs[4][4][16][36];

    const int w    = threadIdx.x >> 5;
    const int lane = threadIdx.x & 31;
    const int ty   = w & 1;
    const int tz   = w >> 1;
    const int x0 = blockIdx.x * 32;
    const int y0 = blockIdx.y * 4;
    const int z0 = blockIdx.z * 4;

    // This warp's 5 load slots: 144 float4 items (16 rows x 9 quads) over 32 lanes
    int s_r[5], s_q[5];
    bool s_on[5];
#pragma unroll
    for (int it = 0; it < 5; ++it) {
        const int idx = lane + it * 32;
        s_on[it] = idx < 144;
        s_r[it] = idx / 9; s_q[it] = idx - s_r[it] * 9;
    }

    auto issue_tile = [&](int c) {   // always commits (empty group past c=31)
        if (c < 32) {
            const int buf = c & 3;
            const float* pfc = g_pf + (size_t)c * 1000000;
#pragma unroll
            for (int it = 0; it < 5; ++it) {
                if (s_on[it]) {
                    const int r = s_r[it];
                    const int zz = 2 * (r >> 2) + tz;
                    const int yy = 2 * (r & 3) + ty;
                    cp_async16(&pfs[buf][w][r][s_q[it] * 4],
                               pfc + ((z0 + zz) * 100 + (y0 + yy)) * 100
                                   + x0 + s_q[it] * 4);
                }
            }
        }
        cp_async_commit();
    };

    size_t pm_off[2][2];
#pragma unroll
    for (int a = 0; a < 2; ++a)
#pragma unroll
        for (int b = 0; b < 2; ++b)
            pm_off[a][b] = (size_t)((z0 + tz + 2 * a) * 96 + (y0 + ty + 2 * b)) * 96
                         + x0 + lane;

    float acc[2][2][27];
#pragma unroll
    for (int a = 0; a < 2; ++a)
#pragma unroll
        for (int b = 0; b < 2; ++b)
#pragma unroll
            for (int d = 0; d < 27; ++d) acc[a][b][d] = 0.f;

    // 3-deep prologue (per-warp private pipeline)
    issue_tile(0);
    issue_tile(1);
    issue_tile(2);

    float pmv[2][2];
#pragma unroll
    for (int a = 0; a < 2; ++a)
#pragma unroll
        for (int b = 0; b < 2; ++b)
            pmv[a][b] = __ldg(g_pm + pm_off[a][b]);

#pragma unroll 1
    for (int c = 0; c < 32; ++c) {
        cp_async_wait<2>();          // this warp's tile c complete
        __syncwarp();                // intra-warp visibility of lane-mates' fills
        issue_tile(c + 3);           // private buf[(c-1)&3]: readers done (program order)

        float pmn[2][2];
        if (c < 31) {
            const float* pmc = g_pm + (size_t)(c + 1) * 884736;
#pragma unroll
            for (int a = 0; a < 2; ++a)
#pragma unroll
                for (int b = 0; b < 2; ++b)
                    pmn[a][b] = __ldg(pmc + pm_off[a][b]);
        }

        const int cur = c & 3;
#pragma unroll
        for (int zp = 0; zp < 4; ++zp)
#pragma unroll
            for (int yp = 0; yp < 4; ++yp) {
                const float* bp = &pfs[cur][w][zp * 4 + yp][lane];
                const float v0 = bp[0];
                const float v1 = bp[2];
                const float v2 = bp[4];
#pragma unroll
                for (int a = 0; a < 2; ++a) {
                    const int i = zp - a;
                    if (i < 0 || i > 2) continue;       // compile-time resolved
#pragma unroll
                    for (int b = 0; b < 2; ++b) {
                        const int j = yp - b;
                        if (j < 0 || j > 2) continue;   // compile-time resolved
                        const float pv = pmv[a][b];
                        acc[a][b][i * 9 + j * 3 + 0] += pv * v0;
                        acc[a][b][i * 9 + j * 3 + 1] += pv * v1;
                        acc[a][b][i * 9 + j * 3 + 2] += pv * v2;
                    }
                }
            }

        if (c < 31) {
#pragma unroll
            for (int a = 0; a < 2; ++a)
#pragma unroll
                for (int b = 0; b < 2; ++b)
                    pmv[a][b] = pmn[a][b];
        }
    }

    const float inv = 1.0f / 27.0f;
#pragma unroll
    for (int a = 0; a < 2; ++a)
#pragma unroll
        for (int b = 0; b < 2; ++b) {
            const size_t base = pm_off[a][b];
#pragma unroll
            for (int d = 0; d < 27; ++d)
                out[(size_t)d * 884736 + base] = acc[a][b][d] * inv;
        }
}

extern "C" void kernel_launch(void* const* d_in, const int* in_sizes, int n_in,
                              void* d_out, int out_size) {
    const float* mov = (const float*)d_in[0];
    const float* fix = (const float*)d_in[1];
    float* out = (float*)d_out;

    box_fused_kernel<<<3291, 256>>>(mov, fix);

    dim3 cgrid(3, 24, 24);   // x tiles of 32, y/z tiles of 4
    corr_kernel<<<cgrid, 128>>>(out);
}